// round 5
// baseline (speedup 1.0000x reference)
#include <cuda_runtime.h>

#define BB 8
#define GG 64
#define PP 32768
#define NC 80
#define NCHUNK 64            // pred chunks per batch (512 preds each)

// per-(batch, chunk) partial argmax keys: (q_bits << 32) | (0xFFFFFFFF - p)
// fully overwritten every run -> no init needed, graph-safe.
__device__ unsigned long long g_partial[BB * NCHUNK * GG];

// Kernel A: per-gt argmax over preds (division-free cross-mult compare) +
// zero-fill of the 84MB cls region. grid = 8*64 = 512 blocks, 256 threads.
// Thread = (gt g = tid&63, replica r = tid>>6); warp lanes share r, so all
// inner-loop smem reads are broadcast. Ordering exactly matches reference
// rounded-quotient argmax: outside a +-1e-6 band cross-mult order == rounded
// order; inside the band (essentially never) exact divs resolve it.
__global__ void __launch_bounds__(256) argmax_zero_kernel(const float* __restrict__ gt,
                                                          const float* __restrict__ pr,
                                                          float* __restrict__ out) {
    __shared__ float4 s_pc[512];    // px1, px2, py1, py2
    __shared__ float  s_pa[512];
    __shared__ unsigned long long s_key[256];   // [replica][gt]

    int tid = threadIdx.x;
    int b = blockIdx.x >> 6;
    int chunk = blockIdx.x & (NCHUNK - 1);
    int pbase = chunk * 512;

    const float4* prv = (const float4*)pr;   // pr_boxes[0] per reference
#pragma unroll
    for (int j = 0; j < 2; j++) {
        int p = j * 256 + tid;
        float4 v = prv[pbase + p];
        s_pc[p] = make_float4(v.x - v.z * 0.5f, v.x + v.z * 0.5f,
                              v.y - v.w * 0.5f, v.y + v.w * 0.5f);
        s_pa[p] = v.z * v.w;
    }

    // zero-fill this block's slice of the cls output; stores drain under compute.
    {
        float4* zc = (float4*)out + (size_t)blockIdx.x * 10240;
        float4 z = make_float4(0.f, 0.f, 0.f, 0.f);
#pragma unroll
        for (int i = 0; i < 40; i++) zc[i * 256 + tid] = z;
    }

    int g = tid & 63, r = tid >> 6;
    const float* grow = gt + (b * GG + g) * 6;
    float cx = grow[0], cy = grow[1], gw = grow[2], gh = grow[3];
    bool valid = (cx != -1.0f);
    float gx1 = cx - gw * 0.5f, gx2 = cx + gw * 0.5f;
    float gy1 = cy - gh * 0.5f, gy2 = cy + gh * 0.5f;
    float ga = gw * gh;
    __syncthreads();

    int base = r * 128;
    float bn = 0.f, bd = 1.f;          // best numerator / denominator
    int bp = pbase + base;             // earliest pred in range
#pragma unroll 8
    for (int i = 0; i < 128; i++) {
        float4 c = s_pc[base + i];              // broadcast LDS.128
        float pa = s_pa[base + i];              // broadcast LDS.32
        float iw = fmaxf(0.f, fminf(gx2, c.y) - fmaxf(gx1, c.x));
        float ih = fmaxf(0.f, fminf(gy2, c.w) - fmaxf(gy1, c.z));
        float inter = iw * ih;
        float den = (ga + pa) - inter + 1e-5f;
        float a  = inter * bd;
        float cc = bn * den;
        bool acc  = a > cc * 1.000001f;
        bool band = !acc && (a >= cc * 0.999999f) && (a != cc);
        if (__any_sync(0xFFFFFFFFu, band)) {    // essentially never taken
            if (band) {
                float qn = inter / den, qo = bn / bd;   // exact rounded compare
                acc = qn > qo;
            }
        }
        if (acc) { bn = inter; bd = den; bp = pbase + base + i; }
    }
    float q = bn / bd;                 // one exact div -> reference-rounded key
    s_key[tid] = valid
        ? (((unsigned long long)__float_as_uint(q) << 32) |
           (unsigned)(0xFFFFFFFFu - (unsigned)bp))
        : 0ULL;
    __syncthreads();

    if (tid < GG) {
        unsigned long long k0 = s_key[tid],       k1 = s_key[tid + 64];
        unsigned long long k2 = s_key[tid + 128], k3 = s_key[tid + 192];
        unsigned long long k = k0 > k1 ? k0 : k1;
        unsigned long long m = k2 > k3 ? k2 : k3;
        k = k > m ? k : m;
        g_partial[(size_t)blockIdx.x * GG + tid] = k;
    }
}

// Kernel B: per-(b,p) assignment. Best-pair contributions handled sparsely in
// staging; inner loop only tests the iou>=0.5 threshold under a warp-vote
// branch. cls region pre-zeroed by kernel A; sparse 1.0 scatter here.
__global__ void __launch_bounds__(256) assign_kernel(const float* __restrict__ gt,
                                                     const float* __restrict__ pr,
                                                     float* __restrict__ out) {
    __shared__ float4 s_box[GG];    // gx1, gx2, gy1, gy2 (compacted valid gts)
    __shared__ float4 s_sum[GG];    // gcx, gcy, log(gw), log(gh)
    __shared__ float  s_ga[GG];
    __shared__ float  s_lab[GG];
    __shared__ unsigned long long s_red[256];
    __shared__ float  s_bw[256], s_bx[256], s_by[256], s_blw[256], s_blh[256];
    __shared__ int    s_bg[256];
    __shared__ int    s_cnt[2];
    __shared__ int    s_ng;

    int tid = threadIdx.x;
    int b = blockIdx.y;

    // zero per-pred best accumulators
    s_bw[tid] = 0.f; s_bx[tid] = 0.f; s_by[tid] = 0.f;
    s_blw[tid] = 0.f; s_blh[tid] = 0.f; s_bg[tid] = -1;

    // reduce 64 argmax partials per gt across 256 threads: (g, quarter)
    {
        int g = tid & 63, qd = tid >> 6;
        unsigned long long k = 0ULL;
        const unsigned long long* src = g_partial + ((size_t)b * NCHUNK + qd * 16) * GG + g;
#pragma unroll
        for (int i = 0; i < 16; i++) {
            unsigned long long v = src[(size_t)i * GG];
            k = v > k ? v : k;
        }
        s_red[tid] = k;
    }

    float cx, cy, w, h, lab, conf;
    bool valid = false;
    int off = 0;
    if (tid < GG) {
        const float* grow = gt + (b * GG + tid) * 6;
        cx = grow[0]; cy = grow[1]; w = grow[2]; h = grow[3];
        lab = grow[4]; conf = grow[5];
        valid = (cx != -1.0f);
        unsigned m = __ballot_sync(0xFFFFFFFFu, valid);
        off = __popc(m & ((1u << (tid & 31)) - 1));
        if ((tid & 31) == 0) s_cnt[tid >> 5] = __popc(m);
    }
    __syncthreads();

    if (tid < GG) {
        if (tid == 0) s_ng = s_cnt[0] + s_cnt[1];
        if (valid) {
            int d = ((tid < 32) ? 0 : s_cnt[0]) + off;   // compacted index
            s_box[d] = make_float4(cx - w * 0.5f, cx + w * 0.5f,
                                   cy - h * 0.5f, cy + h * 0.5f);
            s_sum[d] = make_float4(cx, cy, logf(w), logf(h));
            s_ga[d] = w * h;
            s_lab[d] = lab;
            unsigned long long k0 = s_red[tid],       k1 = s_red[tid + 64];
            unsigned long long k2 = s_red[tid + 128], k3 = s_red[tid + 192];
            unsigned long long k = k0 > k1 ? k0 : k1;
            unsigned long long m2 = k2 > k3 ? k2 : k3;
            k = k > m2 ? k : m2;
            if (conf > 0.f) {
                int bp = (int)(0xFFFFFFFFu - (unsigned)(k & 0xFFFFFFFFull));
                if ((bp >> 8) == (int)blockIdx.x) {      // best pred in this block
                    int lp = bp & 255;
                    atomicAdd(&s_bw[lp], 1.f);
                    atomicAdd(&s_bx[lp], cx);
                    atomicAdd(&s_by[lp], cy);
                    atomicAdd(&s_blw[lp], logf(w));
                    atomicAdd(&s_blh[lp], logf(h));
                    atomicMax(&s_bg[lp], d);
                }
            }
        }
    }
    __syncthreads();
    int ng = s_ng;

    int p = blockIdx.x * 256 + tid;
    float4 pv = ((const float4*)pr)[p];
    float px1 = pv.x - pv.z * 0.5f, px2 = pv.x + pv.z * 0.5f;
    float py1 = pv.y - pv.w * 0.5f, py2 = pv.y + pv.w * 0.5f;
    float pa = pv.z * pv.w;

    int gth = -1;
    bool ign = false;
    float W = 0.f, Scx = 0.f, Scy = 0.f, Slw = 0.f, Slh = 0.f;

#pragma unroll 4
    for (int g = 0; g < ng; g++) {
        float4 bx = s_box[g];                   // broadcast LDS.128
        float ga = s_ga[g];                     // broadcast LDS.32
        float iw = fmaxf(0.f, fminf(bx.y, px2) - fmaxf(bx.x, px1));
        float ih = fmaxf(0.f, fminf(bx.w, py2) - fmaxf(bx.z, py1));
        float inter = iw * ih;
        float den = (ga + pa) - inter + 1e-5f;
        bool th = inter >= 0.5f * den;          // iou >= 0.5, division-free
        ign = ign || ((inter >= 0.4f * den) && !th);
        if (__any_sync(0xFFFFFFFFu, th)) {      // warp-uniform skip, ~96% not taken
            if (th) {
                float4 m = s_sum[g];
                gth = g;                        // ascending -> max index
                W += 1.f;
                Scx += m.x; Scy += m.y; Slw += m.z; Slh += m.w;
            }
        }
    }

    // merge sparse best-pair contributions
    int gbe = s_bg[tid];
    W   += s_bw[tid];
    Scx += s_bx[tid];  Scy += s_by[tid];
    Slw += s_blw[tid]; Slh += s_blh[tid];

    int win = (gbe >= 0) ? gbe : gth;
    bool matched = (win >= 0);
    float mask = matched ? 0.f : 1.f;
    if (ign) mask = -1.f;

    float4 loc;
    if (W > 0.f) {
        loc = make_float4((Scx - W * pv.x) / pv.z,
                          (Scy - W * pv.y) / pv.w,
                          Slw - W * logf(pv.z),
                          Slh - W * logf(pv.w));
    } else {
        loc = make_float4(0.f, 0.f, 0.f, 0.f);   // exact when W==0
    }

    size_t bp_idx = (size_t)b * PP + p;
    float* out_loc  = out + (size_t)BB * PP * NC;
    float* out_mask = out + (size_t)BB * PP * (NC + 4);
    ((float4*)out_loc)[bp_idx] = loc;
    out_mask[bp_idx] = mask;

    if (matched) {                               // sparse one-hot scatter
        int cid = (int)s_lab[win];
        out[((size_t)b * PP + p) * NC + cid] = 1.0f;
    }
}

extern "C" void kernel_launch(void* const* d_in, const int* in_sizes, int n_in,
                              void* d_out, int out_size) {
    const float* gt = (const float*)d_in[0];   // [8,64,6]
    const float* pr = (const float*)d_in[1];   // [8,32768,4]
    float* out = (float*)d_out;                // cls ++ loc ++ mask

    argmax_zero_kernel<<<BB * NCHUNK, 256>>>(gt, pr, out);
    dim3 gridB(PP / 256, BB);
    assign_kernel<<<gridB, 256>>>(gt, pr, out);
}

// round 6
// speedup vs baseline: 1.0345x; 1.0345x over previous
#include <cuda_runtime.h>

#define BB 8
#define GG 64
#define PP 32768
#define NC 80
#define NCHUNK 64            // pred chunks per batch (512 preds each)

// per-(batch, chunk) partial argmax keys: (q_bits << 32) | (0xFFFFFFFF - p)
// fully overwritten every run -> no init needed, graph-safe.
__device__ unsigned long long g_partial[BB * NCHUNK * GG];
__device__ unsigned long long g_final[BB * GG];

// Kernel A: per-gt argmax over preds + zero-fill of the 84MB cls region.
// grid = 8*64 = 512 blocks, 256 threads. Thread = (gt g = tid&63, r = tid>>6);
// warp lanes share r -> all inner-loop smem reads broadcast.
// Inner loop is fully branch-free (no BSSY/BSYNC, no votes): cross-mult
// compare + FSEL updates + sticky near-tie flag. Ties within +-1e-6 relative
// (>> div rounding 6e-8) trigger a post-loop exact-division rescan, so the
// final ordering exactly matches the reference rounded-quotient argmax.
__global__ void __launch_bounds__(256) argmax_zero_kernel(const float* __restrict__ gt,
                                                          const float* __restrict__ pr,
                                                          float* __restrict__ out) {
    __shared__ float4 s_pc[512];    // px1, px2, py1, py2
    __shared__ float  s_pa[512];
    __shared__ unsigned long long s_key[256];

    int tid = threadIdx.x;
    int b = blockIdx.x >> 6;
    int chunk = blockIdx.x & (NCHUNK - 1);
    int pbase = chunk * 512;

    const float4* prv = (const float4*)pr;   // pr_boxes[0] per reference
#pragma unroll
    for (int j = 0; j < 2; j++) {
        int p = j * 256 + tid;
        float4 v = prv[pbase + p];
        s_pc[p] = make_float4(v.x - v.z * 0.5f, v.x + v.z * 0.5f,
                              v.y - v.w * 0.5f, v.y + v.w * 0.5f);
        s_pa[p] = v.z * v.w;
    }

    // zero-fill this block's slice of the cls output; stores drain under compute.
    {
        float4* zc = (float4*)out + (size_t)blockIdx.x * 10240;
        float4 z = make_float4(0.f, 0.f, 0.f, 0.f);
#pragma unroll
        for (int i = 0; i < 40; i++) zc[i * 256 + tid] = z;
    }

    int g = tid & 63, r = tid >> 6;
    const float* grow = gt + (b * GG + g) * 6;
    float cx = grow[0], cy = grow[1], gw = grow[2], gh = grow[3];
    bool valid = (cx != -1.0f);
    float gx1 = cx - gw * 0.5f, gx2 = cx + gw * 0.5f;
    float gy1 = cy - gh * 0.5f, gy2 = cy + gh * 0.5f;
    float gaeps = gw * gh + 1e-5f;
    __syncthreads();

    int base = r * 128;
    float bn = 0.f, bd = 1.f;          // best numerator / denominator
    int bp = base;                     // local index of best (earliest on tie)
    bool band = false;                 // sticky near-tie flag
#pragma unroll 8
    for (int i = 0; i < 128; i++) {
        float4 c = s_pc[base + i];              // broadcast LDS.128
        float pa = s_pa[base + i];              // broadcast LDS.32
        float iw = fmaxf(0.f, fminf(gx2, c.y) - fmaxf(gx1, c.x));
        float ih = fmaxf(0.f, fminf(gy2, c.w) - fmaxf(gy1, c.z));
        float inter = iw * ih;
        float den = (gaeps + pa) - inter;
        float a  = inter * bd;
        float cc = bn * den;
        bool acc = a > cc;
        band = band || ((a != cc) && (a >= cc * 0.999999f) && (a <= cc * 1.000001f));
        bn = acc ? inter : bn;
        bd = acc ? den   : bd;
        bp = acc ? base + i : bp;
    }
    // near-tie fallback: exact rounded-quotient rescan (essentially never taken)
    if (__any_sync(0xFFFFFFFFu, band)) {
        if (band) {
            float bq = 0.f; int bp2 = base;
            for (int i = 0; i < 128; i++) {
                float4 c = s_pc[base + i];
                float pa = s_pa[base + i];
                float iw = fmaxf(0.f, fminf(gx2, c.y) - fmaxf(gx1, c.x));
                float ih = fmaxf(0.f, fminf(gy2, c.w) - fmaxf(gy1, c.z));
                float inter = iw * ih;
                float den = (gaeps + pa) - inter;
                float q = inter / den;
                if (q > bq) { bq = q; bp2 = base + i; }
            }
            bn = bq; bd = 1.f; bp = bp2;
        }
    }
    float q = bn / bd;                 // exact div -> reference-rounded key
    s_key[tid] = valid
        ? (((unsigned long long)__float_as_uint(q) << 32) |
           (unsigned)(0xFFFFFFFFu - (unsigned)(pbase + bp)))
        : 0ULL;
    __syncthreads();

    if (tid < GG) {
        unsigned long long k0 = s_key[tid],       k1 = s_key[tid + 64];
        unsigned long long k2 = s_key[tid + 128], k3 = s_key[tid + 192];
        unsigned long long k = k0 > k1 ? k0 : k1;
        unsigned long long m = k2 > k3 ? k2 : k3;
        k = k > m ? k : m;
        g_partial[(size_t)blockIdx.x * GG + tid] = k;
    }
}

// Kernel A2: reduce 64 chunk-partials -> one key per (b, g). grid 8 x 256.
__global__ void reduce_kernel() {
    __shared__ unsigned long long s_red[256];
    int tid = threadIdx.x;
    int b = blockIdx.x;
    int g = tid & 63, qd = tid >> 6;
    unsigned long long k = 0ULL;
    const unsigned long long* src = g_partial + ((size_t)b * NCHUNK + qd * 16) * GG + g;
#pragma unroll
    for (int i = 0; i < 16; i++) {
        unsigned long long v = src[(size_t)i * GG];
        k = v > k ? v : k;
    }
    s_red[tid] = k;
    __syncthreads();
    if (tid < GG) {
        unsigned long long k0 = s_red[tid],       k1 = s_red[tid + 64];
        unsigned long long k2 = s_red[tid + 128], k3 = s_red[tid + 192];
        unsigned long long a = k0 > k1 ? k0 : k1;
        unsigned long long c = k2 > k3 ? k2 : k3;
        g_final[b * GG + tid] = a > c ? a : c;
    }
}

// Kernel B: per-(b,p) assignment. Fully predicated inner loop (no votes, no
// branches). Best-pair contributions scattered sparsely during staging.
// cls region pre-zeroed by kernel A; sparse 1.0 scatter here.
__global__ void __launch_bounds__(256) assign_kernel(const float* __restrict__ gt,
                                                     const float* __restrict__ pr,
                                                     float* __restrict__ out) {
    __shared__ float4 s_box[GG];    // gx1, gx2, gy1, gy2 (compacted valid gts)
    __shared__ float4 s_sum[GG];    // gcx, gcy, log(gw), log(gh)
    __shared__ float  s_S[GG];      // ga + 1e-5
    __shared__ float  s_lab[GG];
    __shared__ float  s_bw[256], s_bx[256], s_by[256], s_blw[256], s_blh[256];
    __shared__ int    s_bg[256];
    __shared__ int    s_cnt[2];
    __shared__ int    s_ng;

    int tid = threadIdx.x;
    int b = blockIdx.y;

    s_bw[tid] = 0.f; s_bx[tid] = 0.f; s_by[tid] = 0.f;
    s_blw[tid] = 0.f; s_blh[tid] = 0.f; s_bg[tid] = -1;

    float cx, cy, w, h, lab, conf;
    bool valid = false;
    int off = 0;
    if (tid < GG) {
        const float* grow = gt + (b * GG + tid) * 6;
        cx = grow[0]; cy = grow[1]; w = grow[2]; h = grow[3];
        lab = grow[4]; conf = grow[5];
        valid = (cx != -1.0f);
        unsigned m = __ballot_sync(0xFFFFFFFFu, valid);
        off = __popc(m & ((1u << (tid & 31)) - 1));
        if ((tid & 31) == 0) s_cnt[tid >> 5] = __popc(m);
    }
    __syncthreads();

    if (tid < GG) {
        if (tid == 0) s_ng = s_cnt[0] + s_cnt[1];
        if (valid) {
            int d = ((tid < 32) ? 0 : s_cnt[0]) + off;   // compacted index
            s_box[d] = make_float4(cx - w * 0.5f, cx + w * 0.5f,
                                   cy - h * 0.5f, cy + h * 0.5f);
            s_sum[d] = make_float4(cx, cy, logf(w), logf(h));
            s_S[d] = w * h + 1e-5f;
            s_lab[d] = lab;
            if (conf > 0.f) {
                unsigned long long k = g_final[b * GG + tid];
                int bp = (int)(0xFFFFFFFFu - (unsigned)(k & 0xFFFFFFFFull));
                if ((bp >> 8) == (int)blockIdx.x) {      // best pred in this block
                    int lp = bp & 255;
                    atomicAdd(&s_bw[lp], 1.f);
                    atomicAdd(&s_bx[lp], cx);
                    atomicAdd(&s_by[lp], cy);
                    atomicAdd(&s_blw[lp], logf(w));
                    atomicAdd(&s_blh[lp], logf(h));
                    atomicMax(&s_bg[lp], d);
                }
            }
        }
    }
    __syncthreads();
    int ng = s_ng;

    int p = blockIdx.x * 256 + tid;
    float4 pv = ((const float4*)pr)[p];
    float px1 = pv.x - pv.z * 0.5f, px2 = pv.x + pv.z * 0.5f;
    float py1 = pv.y - pv.w * 0.5f, py2 = pv.y + pv.w * 0.5f;
    float pa = pv.z * pv.w;

    int gth = -1;
    bool ign = false;
    float W = 0.f, Scx = 0.f, Scy = 0.f, Slw = 0.f, Slh = 0.f;

#pragma unroll 4
    for (int g = 0; g < ng; g++) {
        float4 bx = s_box[g];                   // broadcast LDS.128
        float S  = s_S[g];                      // broadcast LDS.32
        float4 m = s_sum[g];                    // broadcast LDS.128
        float iw = fmaxf(0.f, fminf(bx.y, px2) - fmaxf(bx.x, px1));
        float ih = fmaxf(0.f, fminf(bx.w, py2) - fmaxf(bx.z, py1));
        float inter = iw * ih;
        float den = (S + pa) - inter;
        bool th = inter >= 0.5f * den;          // iou >= 0.5, division-free
        ign = ign || ((inter >= 0.4f * den) && !th);
        float wgt = th ? 1.f : 0.f;
        gth = th ? g : gth;
        W   += wgt;
        Scx += wgt * m.x;
        Scy += wgt * m.y;
        Slw += wgt * m.z;
        Slh += wgt * m.w;
    }

    // merge sparse best-pair contributions
    int gbe = s_bg[tid];
    W   += s_bw[tid];
    Scx += s_bx[tid];  Scy += s_by[tid];
    Slw += s_blw[tid]; Slh += s_blh[tid];

    int win = (gbe >= 0) ? gbe : gth;
    bool matched = (win >= 0);
    float mask = matched ? 0.f : 1.f;
    if (ign) mask = -1.f;

    float4 loc;
    if (W > 0.f) {
        loc = make_float4((Scx - W * pv.x) / pv.z,
                          (Scy - W * pv.y) / pv.w,
                          Slw - W * logf(pv.z),
                          Slh - W * logf(pv.w));
    } else {
        loc = make_float4(0.f, 0.f, 0.f, 0.f);   // exact when W==0
    }

    size_t bp_idx = (size_t)b * PP + p;
    float* out_loc  = out + (size_t)BB * PP * NC;
    float* out_mask = out + (size_t)BB * PP * (NC + 4);
    ((float4*)out_loc)[bp_idx] = loc;
    out_mask[bp_idx] = mask;

    if (matched) {                               // sparse one-hot scatter
        int cid = (int)s_lab[win];
        out[((size_t)b * PP + p) * NC + cid] = 1.0f;
    }
}

extern "C" void kernel_launch(void* const* d_in, const int* in_sizes, int n_in,
                              void* d_out, int out_size) {
    const float* gt = (const float*)d_in[0];   // [8,64,6]
    const float* pr = (const float*)d_in[1];   // [8,32768,4]
    float* out = (float*)d_out;                // cls ++ loc ++ mask

    argmax_zero_kernel<<<BB * NCHUNK, 256>>>(gt, pr, out);
    reduce_kernel<<<BB, 256>>>();
    dim3 gridB(PP / 256, BB);
    assign_kernel<<<gridB, 256>>>(gt, pr, out);
}

// round 7
// speedup vs baseline: 1.2493x; 1.2076x over previous
#include <cuda_runtime.h>

#define BB 8
#define GG 64
#define PP 32768
#define NC 80
#define NCHUNK 128           // pred chunks per batch (256 preds each)

// per-(batch, chunk) partial argmax keys: (q_bits << 32) | (0xFFFFFFFF - p)
// all scratch fully overwritten every run -> no init needed, graph-safe.
__device__ unsigned long long g_partial[BB * NCHUNK * GG];
__device__ unsigned long long g_final[BB * GG];
__device__ float4 g_rec[BB * PP * 2];   // per-(b,p): {W,Scx,Scy,Slw},{Slh,gth,ign,0}

// Kernel A: one pass over all (g, p) pairs of this block's 256 preds.
// Thread = (gt g = tid&63, r = tid>>6) scanning 64 preds in 2 independent
// argmax sub-chains (cross-mult compare, FSEL updates, sticky near-tie band
// resolved by exact-division rescan -> ordering == reference rounded-quotient
// argmax). th / ignore events recorded as 64-bit masks, drained post-loop via
// rare smem atomics into per-pred accumulators. Also zero-fills cls slice.
__global__ void __launch_bounds__(256) fused_kernel(const float* __restrict__ gt,
                                                    const float* __restrict__ pr,
                                                    float* __restrict__ out) {
    __shared__ float4 s_pc[256];    // px1, px2, py1, py2
    __shared__ float  s_pa[256];
    __shared__ float  s_W[256], s_cx[256], s_cy[256], s_lw[256], s_lh[256];
    __shared__ int    s_gth[256], s_ign[256];
    __shared__ unsigned long long s_key[256];

    int tid = threadIdx.x;
    int b = blockIdx.x >> 7;
    int chunk = blockIdx.x & (NCHUNK - 1);
    int pbase = chunk * 256;

    {   // stage preds
        float4 v = ((const float4*)pr)[pbase + tid];   // pr_boxes[0] per reference
        s_pc[tid] = make_float4(v.x - v.z * 0.5f, v.x + v.z * 0.5f,
                                v.y - v.w * 0.5f, v.y + v.w * 0.5f);
        s_pa[tid] = v.z * v.w;
    }
    s_W[tid] = 0.f; s_cx[tid] = 0.f; s_cy[tid] = 0.f;
    s_lw[tid] = 0.f; s_lh[tid] = 0.f;
    s_gth[tid] = -1; s_ign[tid] = 0;

    {   // zero-fill this block's cls slice; stores drain under compute
        float4* zc = (float4*)out + (size_t)blockIdx.x * 5120;
        float4 z = make_float4(0.f, 0.f, 0.f, 0.f);
#pragma unroll
        for (int i = 0; i < 20; i++) zc[i * 256 + tid] = z;
    }

    int g = tid & 63, r = tid >> 6;
    const float* grow = gt + (b * GG + g) * 6;
    float cx = grow[0], cy = grow[1], gw = grow[2], gh = grow[3];
    bool valid = (cx != -1.0f);
    float gx1 = cx - gw * 0.5f, gx2 = cx + gw * 0.5f;
    float gy1 = cy - gh * 0.5f, gy2 = cy + gh * 0.5f;
    float gaeps = gw * gh + 1e-5f;
    // invalid gt (cx=-1): corners are inverted -> iw/ih clamp to 0, inter=0,
    // den>0, so th/ign stay false and argmax key is gated by 'valid'.
    __syncthreads();

    int base = r * 64;
    float bn0 = 0.f, bd0 = 1.f; int bp0 = base;        // sub-chain 0: preds base+0..31
    float bn1 = 0.f, bd1 = 1.f; int bp1 = base + 32;   // sub-chain 1: preds base+32..63
    unsigned mth0 = 0, mig0 = 0, mth1 = 0, mig1 = 0;
    bool band = false;

#pragma unroll 8
    for (int i = 0; i < 32; i++) {
        unsigned bit = 1u << i;
        {   // chain 0
            float4 c = s_pc[base + i];
            float pa = s_pa[base + i];
            float iw = fmaxf(0.f, fminf(gx2, c.y) - fmaxf(gx1, c.x));
            float ih = fmaxf(0.f, fminf(gy2, c.w) - fmaxf(gy1, c.z));
            float inter = iw * ih;
            float den = (gaeps + pa) - inter;
            float a = inter * bd0, cc = bn0 * den;
            bool acc = a > cc;
            float d = a - cc;
            band = band || ((d != 0.f) && (fabsf(d) <= cc * 1e-6f));
            bn0 = acc ? inter : bn0;
            bd0 = acc ? den : bd0;
            bp0 = acc ? base + i : bp0;
            bool th = inter >= 0.5f * den;
            bool ig = (inter >= 0.4f * den) && !th;
            mth0 |= th ? bit : 0u;
            mig0 |= ig ? bit : 0u;
        }
        {   // chain 1
            float4 c = s_pc[base + 32 + i];
            float pa = s_pa[base + 32 + i];
            float iw = fmaxf(0.f, fminf(gx2, c.y) - fmaxf(gx1, c.x));
            float ih = fmaxf(0.f, fminf(gy2, c.w) - fmaxf(gy1, c.z));
            float inter = iw * ih;
            float den = (gaeps + pa) - inter;
            float a = inter * bd1, cc = bn1 * den;
            bool acc = a > cc;
            float d = a - cc;
            band = band || ((d != 0.f) && (fabsf(d) <= cc * 1e-6f));
            bn1 = acc ? inter : bn1;
            bd1 = acc ? den : bd1;
            bp1 = acc ? base + 32 + i : bp1;
            bool th = inter >= 0.5f * den;
            bool ig = (inter >= 0.4f * den) && !th;
            mth1 |= th ? bit : 0u;
            mig1 |= ig ? bit : 0u;
        }
    }
    {   // merge chains (chain0 holds lower indices -> keep on tie)
        float a = bn1 * bd0, cc = bn0 * bd1;
        bool acc = a > cc;
        float d = a - cc;
        band = band || ((d != 0.f) && (fabsf(d) <= cc * 1e-6f));
        if (acc) { bn0 = bn1; bd0 = bd1; bp0 = bp1; }
    }
    // near-tie fallback: exact rounded-quotient rescan (essentially never taken)
    if (__any_sync(0xFFFFFFFFu, band)) {
        if (band) {
            float bq = 0.f; int bp2 = base;
            for (int i = 0; i < 64; i++) {
                float4 c = s_pc[base + i];
                float pa = s_pa[base + i];
                float iw = fmaxf(0.f, fminf(gx2, c.y) - fmaxf(gx1, c.x));
                float ih = fmaxf(0.f, fminf(gy2, c.w) - fmaxf(gy1, c.z));
                float inter = iw * ih;
                float den = (gaeps + pa) - inter;
                float q = inter / den;
                if (q > bq) { bq = q; bp2 = base + i; }
            }
            bn0 = bq; bd0 = 1.f; bp0 = bp2;
        }
    }
    float q = bn0 / bd0;               // one exact div -> reference-rounded key
    s_key[tid] = valid
        ? (((unsigned long long)__float_as_uint(q) << 32) |
           (unsigned)(0xFFFFFFFFu - (unsigned)(pbase + bp0)))
        : 0ULL;

    // drain rare th / ignore events into per-pred accumulators
    unsigned long long thm = ((unsigned long long)mth1 << 32) | mth0;
    unsigned long long igm = ((unsigned long long)mig1 << 32) | mig0;
    if (!valid) { thm = 0ULL; igm = 0ULL; }
    if (thm) {
        float lw = logf(gw), lh = logf(gh);
        do {
            int i = __ffsll(thm) - 1; thm &= thm - 1;
            int pp = base + i;
            atomicAdd(&s_W[pp], 1.f);
            atomicAdd(&s_cx[pp], cx);
            atomicAdd(&s_cy[pp], cy);
            atomicAdd(&s_lw[pp], lw);
            atomicAdd(&s_lh[pp], lh);
            atomicMax(&s_gth[pp], g);
        } while (thm);
    }
    while (igm) {
        int i = __ffsll(igm) - 1; igm &= igm - 1;
        s_ign[base + i] = 1;            // benign race: all writers store 1
    }
    __syncthreads();

    if (tid < GG) {                     // per-(block, gt) argmax partial
        unsigned long long k0 = s_key[tid],       k1 = s_key[tid + 64];
        unsigned long long k2 = s_key[tid + 128], k3 = s_key[tid + 192];
        unsigned long long k = k0 > k1 ? k0 : k1;
        unsigned long long m = k2 > k3 ? k2 : k3;
        k = k > m ? k : m;
        g_partial[(size_t)blockIdx.x * GG + tid] = k;
    }

    size_t idx = (size_t)b * PP + pbase + tid;      // per-pred record
    g_rec[idx * 2]     = make_float4(s_W[tid], s_cx[tid], s_cy[tid], s_lw[tid]);
    g_rec[idx * 2 + 1] = make_float4(s_lh[tid], __int_as_float(s_gth[tid]),
                                     __int_as_float(s_ign[tid]), 0.f);
}

// Kernel A2: reduce 128 chunk-partials -> one key per (b, g). grid 8 x 256.
__global__ void reduce_kernel() {
    __shared__ unsigned long long s_red[256];
    int tid = threadIdx.x;
    int b = blockIdx.x;
    int g = tid & 63, qd = tid >> 6;
    unsigned long long k = 0ULL;
    const unsigned long long* src = g_partial + ((size_t)b * NCHUNK + qd * 32) * GG + g;
#pragma unroll
    for (int i = 0; i < 32; i++) {
        unsigned long long v = src[(size_t)i * GG];
        k = v > k ? v : k;
    }
    s_red[tid] = k;
    __syncthreads();
    if (tid < GG) {
        unsigned long long k0 = s_red[tid],       k1 = s_red[tid + 64];
        unsigned long long k2 = s_red[tid + 128], k3 = s_red[tid + 192];
        unsigned long long a = k0 > k1 ? k0 : k1;
        unsigned long long c = k2 > k3 ? k2 : k3;
        g_final[b * GG + tid] = a > c ? a : c;
    }
}

// Kernel B: merge best-pair term + finalize. No per-gt loop. grid (128, 8).
__global__ void __launch_bounds__(256) finalize_kernel(const float* __restrict__ gt,
                                                       const float* __restrict__ pr,
                                                       float* __restrict__ out) {
    __shared__ float s_bw[256], s_bx[256], s_by[256], s_blw[256], s_blh[256];
    __shared__ int   s_bg[256];
    __shared__ float s_lab[GG];

    int tid = threadIdx.x;
    int b = blockIdx.y;

    s_bw[tid] = 0.f; s_bx[tid] = 0.f; s_by[tid] = 0.f;
    s_blw[tid] = 0.f; s_blh[tid] = 0.f; s_bg[tid] = -1;

    if (tid < GG) {
        const float* grow = gt + (b * GG + tid) * 6;
        float cx = grow[0];
        s_lab[tid] = grow[4];
        bool valid = (cx != -1.0f);
        float conf = grow[5];
        if (valid && conf > 0.f) {
            unsigned long long k = g_final[b * GG + tid];
            int bp = (int)(0xFFFFFFFFu - (unsigned)(k & 0xFFFFFFFFull));
            if ((bp >> 8) == (int)blockIdx.x) {     // best pred lives in this block
                int lp = bp & 255;
                atomicAdd(&s_bw[lp], 1.f);
                atomicAdd(&s_bx[lp], cx);
                atomicAdd(&s_by[lp], grow[1]);
                atomicAdd(&s_blw[lp], logf(grow[2]));
                atomicAdd(&s_blh[lp], logf(grow[3]));
                atomicMax(&s_bg[lp], tid);          // original gt index (monotone)
            }
        }
    }
    __syncthreads();

    int p = blockIdx.x * 256 + tid;
    size_t idx = (size_t)b * PP + p;
    float4 r0 = g_rec[idx * 2];
    float4 r1 = g_rec[idx * 2 + 1];

    float W   = r0.x + s_bw[tid];
    float Scx = r0.y + s_bx[tid];
    float Scy = r0.z + s_by[tid];
    float Slw = r0.w + s_blw[tid];
    float Slh = r1.x + s_blh[tid];
    int gth = __float_as_int(r1.y);
    bool ign = __float_as_int(r1.z) != 0;
    int gbe = s_bg[tid];

    int win = (gbe >= 0) ? gbe : gth;
    bool matched = (win >= 0);
    float mask = matched ? 0.f : 1.f;
    if (ign) mask = -1.f;

    float4 pv = ((const float4*)pr)[p];
    float4 loc;
    if (W > 0.f) {
        loc = make_float4((Scx - W * pv.x) / pv.z,
                          (Scy - W * pv.y) / pv.w,
                          Slw - W * logf(pv.z),
                          Slh - W * logf(pv.w));
    } else {
        loc = make_float4(0.f, 0.f, 0.f, 0.f);      // exact: sums are 0 when W==0
    }

    float* out_loc  = out + (size_t)BB * PP * NC;
    float* out_mask = out + (size_t)BB * PP * (NC + 4);
    ((float4*)out_loc)[idx] = loc;
    out_mask[idx] = mask;

    if (matched) {                                  // sparse one-hot scatter
        int cid = (int)s_lab[win];
        out[idx * NC + cid] = 1.0f;
    }
}

extern "C" void kernel_launch(void* const* d_in, const int* in_sizes, int n_in,
                              void* d_out, int out_size) {
    const float* gt = (const float*)d_in[0];   // [8,64,6]
    const float* pr = (const float*)d_in[1];   // [8,32768,4]
    float* out = (float*)d_out;                // cls ++ loc ++ mask

    fused_kernel<<<BB * NCHUNK, 256>>>(gt, pr, out);
    reduce_kernel<<<BB, 256>>>();
    dim3 gridB(PP / 256, BB);
    finalize_kernel<<<gridB, 256>>>(gt, pr, out);
}